// round 10
// baseline (speedup 1.0000x reference)
#include <cuda_runtime.h>
#include <math.h>
#include <stdint.h>

#define T_LEN 256
#define G4    1024
#define D_IN  768
#define D_L   512
#define NROWS 8192
#define XZS   (NROWS * G4)
typedef unsigned long long ull;

__device__ float g_xz[2 * XZS];
__device__ float g_h [NROWS * D_L];
__device__ float g_hc[NROWS * 1024];
__device__ float g_sq[NROWS * 10];
__device__ float g_sk[NROWS * 10];

__device__ __forceinline__ void fma2(ull& d, ull a, ull b) {
    asm("fma.rn.f32x2 %0, %1, %2, %0;" : "+l"(d) : "l"(a), "l"(b));
}
__device__ __forceinline__ float hsum2(ull v) {
    float lo, hi; asm("mov.b64 {%0,%1}, %2;" : "=f"(lo), "=f"(hi) : "l"(v));
    return lo + hi;
}
__device__ __forceinline__ float fsig(float x) {
    return __fdividef(1.0f, 1.0f + __expf(-x));
}
__device__ __forceinline__ float ftanh(float x) {
    return fmaf(2.0f, fsig(2.0f * x), -1.0f);
}
__device__ __forceinline__ float htanh(float x) {
    float r; asm("tanh.approx.f32 %0, %1;" : "=f"(r) : "f"(x)); return r;
}
__device__ __forceinline__ uint32_t f2tf(float x) {
    uint32_t r; asm("cvt.rna.tf32.f32 %0, %1;" : "=r"(r) : "f"(x)); return r;
}
__device__ __forceinline__ uint32_t smem_u32(const void* p) {
    uint32_t a;
    asm("{ .reg .u64 t; cvta.to.shared.u64 t, %1; cvt.u32.u64 %0, t; }" : "=r"(a) : "l"(p));
    return a;
}
__device__ __forceinline__ uint32_t mapa_u32(uint32_t a, uint32_t rank) {
    uint32_t r; asm("mapa.shared::cluster.u32 %0, %1, %2;" : "=r"(r) : "r"(a), "r"(rank));
    return r;
}
__device__ __forceinline__ void st_remote_f32(uint32_t addr, float v) {
    asm volatile("st.shared::cluster.f32 [%0], %1;" :: "r"(addr), "f"(v) : "memory");
}
__device__ __forceinline__ void mbar_init(uint32_t a, unsigned n) {
    asm volatile("mbarrier.init.shared.b64 [%0], %1;" :: "r"(a), "r"(n) : "memory");
}
__device__ __forceinline__ void mbar_arrive_remote(uint32_t a) {
    asm volatile("mbarrier.arrive.release.cluster.shared::cluster.b64 _, [%0];" :: "r"(a) : "memory");
}
__device__ __forceinline__ void fence_cluster() {
    asm volatile("fence.acq_rel.cluster;" ::: "memory");
}
__device__ __forceinline__ void mbar_wait(uint32_t a, unsigned ph) {
    unsigned done;
    do {
        asm volatile("{\n\t.reg .pred p;\n\t"
            "mbarrier.try_wait.parity.acquire.cluster.shared::cta.b64 p, [%1], %2, 0x989680;\n\t"
            "selp.b32 %0, 1, 0, p;\n\t}" : "=r"(done) : "r"(a), "r"(ph) : "memory");
    } while (!done);
}

// ---- tf32 tensor-core GEMM (unchanged) ----
__global__ __launch_bounds__(256) void k_gemm(const float* __restrict__ A, int Kdim,
                                              const float* __restrict__ W0,
                                              const float* __restrict__ b0,
                                              float* __restrict__ C0,
                                              const float* __restrict__ W1,
                                              const float* __restrict__ b1,
                                              float* __restrict__ C1, int ldc) {
    __shared__ uint32_t As[2][8][136], Bs[2][8][136];
    const float* W    = blockIdx.z ? W1 : W0;
    const float* bias = blockIdx.z ? b1 : b0;
    float*       C    = blockIdx.z ? C1 : C0;
    int tid = threadIdx.x, lane = tid & 31, wid = tid >> 5;
    int m0 = blockIdx.y * 128, n0 = blockIdx.x * 128;
    int mb = (wid >> 2) * 64, nb = (wid & 3) * 32;
    int ar = tid >> 1, ak = (tid & 1) * 4;
    const float* Arow = A + (size_t)(m0 + ar) * Kdim + ak;
    const float* Brow = W + (size_t)(n0 + ar) * Kdim + ak;
    float acc[4][4][4];
#pragma unroll
    for (int i = 0; i < 4; i++)
#pragma unroll
        for (int j = 0; j < 4; j++)
#pragma unroll
            for (int c = 0; c < 4; c++) acc[i][j][c] = 0.f;
    int kq = lane & 3, gq = lane >> 2;
    float4 av = *(const float4*)(Arow);
    float4 bv = *(const float4*)(Brow);
    int buf = 0;
    for (int k0 = 0; k0 < Kdim; k0 += 8) {
        As[buf][ak + 0][ar] = f2tf(av.x); As[buf][ak + 1][ar] = f2tf(av.y);
        As[buf][ak + 2][ar] = f2tf(av.z); As[buf][ak + 3][ar] = f2tf(av.w);
        Bs[buf][ak + 0][ar] = f2tf(bv.x); Bs[buf][ak + 1][ar] = f2tf(bv.y);
        Bs[buf][ak + 2][ar] = f2tf(bv.z); Bs[buf][ak + 3][ar] = f2tf(bv.w);
        __syncthreads();
        if (k0 + 8 < Kdim) {
            av = *(const float4*)(Arow + k0 + 8);
            bv = *(const float4*)(Brow + k0 + 8);
        }
        uint32_t a[4][4], b[4][2];
#pragma unroll
        for (int mf = 0; mf < 4; mf++) {
            int r = mb + mf * 16 + gq;
            a[mf][0] = As[buf][kq][r];     a[mf][1] = As[buf][kq][r + 8];
            a[mf][2] = As[buf][kq + 4][r]; a[mf][3] = As[buf][kq + 4][r + 8];
        }
#pragma unroll
        for (int nf = 0; nf < 4; nf++) {
            int c = nb + nf * 8 + gq;
            b[nf][0] = Bs[buf][kq][c]; b[nf][1] = Bs[buf][kq + 4][c];
        }
#pragma unroll
        for (int mf = 0; mf < 4; mf++)
#pragma unroll
            for (int nf = 0; nf < 4; nf++)
                asm volatile(
                    "mma.sync.aligned.m16n8k8.row.col.f32.tf32.tf32.f32 "
                    "{%0,%1,%2,%3}, {%4,%5,%6,%7}, {%8,%9}, {%0,%1,%2,%3};"
                    : "+f"(acc[mf][nf][0]), "+f"(acc[mf][nf][1]),
                      "+f"(acc[mf][nf][2]), "+f"(acc[mf][nf][3])
                    : "r"(a[mf][0]), "r"(a[mf][1]), "r"(a[mf][2]), "r"(a[mf][3]),
                      "r"(b[nf][0]), "r"(b[nf][1]));
        buf ^= 1;
        __syncthreads();
    }
#pragma unroll
    for (int mf = 0; mf < 4; mf++)
#pragma unroll
        for (int nf = 0; nf < 4; nf++) {
            int row = m0 + mb + mf * 16 + gq;
            int col = n0 + nb + nf * 8 + 2 * kq;
            float b0v = bias[col], b1v = bias[col + 1];
            float* p0 = C + (size_t)row * ldc + col;
            float* p1 = C + (size_t)(row + 8) * ldc + col;
            p0[0] = acc[mf][nf][0] + b0v; p0[1] = acc[mf][nf][1] + b1v;
            p1[0] = acc[mf][nf][2] + b0v; p1[1] = acc[mf][nf][3] + b1v;
        }
}

// ---- persistent LSTM: 16 clusters x 8 CTAs, DSMEM h-exchange, reg weights ----
__global__ __launch_bounds__(256) __cluster_dims__(8, 1, 1)
void k_lstm(const float* __restrict__ Whf, const float* __restrict__ Whb) {
    __shared__ float hbuf[2][4][256];           // [buf][batch][unit]
    __shared__ float zp[4 * 640];               // [kseg][row*5 + b]
    __shared__ __align__(8) ull mbar[2];

    int tid = threadIdx.x;
    uint32_t rank; asm("mov.u32 %0, %%cluster_ctarank;" : "=r"(rank));
    int cid = blockIdx.x >> 3;
    int dir = cid >> 3, grp = cid & 7;
    int B0 = grp * 4, U0 = (int)rank * 32;
    const float* Whh = dir ? Whb : Whf;

    uint32_t mb_u32 = smem_u32(&mbar[0]);
    uint32_t hb_u32 = smem_u32(&hbuf[0][0][0]);
    if (tid == 0) { mbar_init(mb_u32, 8); mbar_init(mb_u32 + 8, 8); }
    asm volatile("barrier.cluster.arrive.aligned;" ::: "memory");
    asm volatile("barrier.cluster.wait.aligned;" ::: "memory");

    // weights in registers: thread = (kseg 0..3, rowgroup 0..63) -> rows 2rg, 2rg+1
    int kseg = tid & 3, rg = tid >> 2;
    int r0 = rg * 2, r1 = r0 + 1;
    ull w0[32], w1[32];
    {
        const ulonglong2* q0 = (const ulonglong2*)(Whh +
            (size_t)((r0 >> 5) * 256 + U0 + (r0 & 31)) * 256 + kseg * 64);
        const ulonglong2* q1 = (const ulonglong2*)(Whh +
            (size_t)((r1 >> 5) * 256 + U0 + (r1 & 31)) * 256 + kseg * 64);
#pragma unroll
        for (int i = 0; i < 16; i++) {
            ulonglong2 v0 = q0[i], v1 = q1[i];
            w0[2 * i] = v0.x; w0[2 * i + 1] = v0.y;
            w1[2 * i] = v1.x; w1[2 * i + 1] = v1.y;
        }
    }

    int u = tid & 31, ab = tid >> 5;            // activation mapping (tid<128)
    const float* xz = g_xz + (size_t)dir * XZS;
    float c_reg = 0.f;

    for (int s = 0; s < T_LEN; s++) {
        int t = dir ? (T_LEN - 1 - s) : s;
        // prefetch xz before waiting
        float xzv[4];
        if (tid < 128) {
            const float* xzp = xz + (size_t)((B0 + ab) * T_LEN + t) * G4 + U0 + u;
#pragma unroll
            for (int g = 0; g < 4; g++) xzv[g] = xzp[g * 256];
        }

        if (s > 0) {
            int pb = (s - 1) & 1;
            mbar_wait(mb_u32 + 8 * pb, ((s - 1) >> 1) & 1);
            const float* hb = &hbuf[pb][0][0];
            ull acc[2][4];
#pragma unroll
            for (int i = 0; i < 2; i++)
#pragma unroll
                for (int b = 0; b < 4; b++) acc[i][b] = 0ull;
#pragma unroll
            for (int c = 0; c < 8; c++) {       // 8-float k chunks
                ull hr[4][4];
#pragma unroll
                for (int b = 0; b < 4; b++) {
                    const ulonglong2* hp =
                        (const ulonglong2*)(hb + b * 256 + kseg * 64 + c * 8);
                    ulonglong2 v0 = hp[0], v1 = hp[1];
                    hr[b][0] = v0.x; hr[b][1] = v0.y; hr[b][2] = v1.x; hr[b][3] = v1.y;
                }
#pragma unroll
                for (int kk = 0; kk < 4; kk++) {
                    ull wa = w0[c * 4 + kk], wb = w1[c * 4 + kk];
#pragma unroll
                    for (int b = 0; b < 4; b++) {
                        fma2(acc[0][b], wa, hr[b][kk]);
                        fma2(acc[1][b], wb, hr[b][kk]);
                    }
                }
            }
#pragma unroll
            for (int b = 0; b < 4; b++) {
                zp[kseg * 640 + r0 * 5 + b] = hsum2(acc[0][b]);
                zp[kseg * 640 + r1 * 5 + b] = hsum2(acc[1][b]);
            }
        }
        __syncthreads();

        if (tid < 128) {
            float z[4];
#pragma unroll
            for (int g = 0; g < 4; g++) {
                float zv = xzv[g];
                if (s > 0) {
                    int base = (g * 32 + u) * 5 + ab;
#pragma unroll
                    for (int ks = 0; ks < 4; ks++) zv += zp[ks * 640 + base];
                }
                z[g] = zv;
            }
            c_reg = fmaf(fsig(z[1]), c_reg, fsig(z[0]) * ftanh(z[2]));
            float h = fsig(z[3]) * ftanh(c_reg);
            g_h[(size_t)((B0 + ab) * T_LEN + t) * D_L + dir * 256 + U0 + u] = h;
            if (s < T_LEN - 1) {
                uint32_t loc = hb_u32 + (((s & 1) * 4 + ab) * 256 + U0 + u) * 4;
#pragma unroll
                for (uint32_t p = 0; p < 8; p++) st_remote_f32(mapa_u32(loc, p), h);
            }
        }
        __syncthreads();                        // DSMEM stores + zp reads done
        if (s < T_LEN - 1 && tid < 8) {
            fence_cluster();
            mbar_arrive_remote(mapa_u32(mb_u32 + 8 * (s & 1), (uint32_t)tid));
        }
    }
}

// ---- sq/sk projections + copy h into concat buffer (unchanged) ----
__global__ __launch_bounds__(256) void k_sqsk(const float* __restrict__ W1) {
    __shared__ float W1s[10 * 1024];
    int tid = threadIdx.x;
    for (int i = tid; i < 2560; i += 256) ((float4*)W1s)[i] = ((const float4*)W1)[i];
    __syncthreads();
    int w = tid >> 5, l = tid & 31;
    int row = blockIdx.x * 8 + w;
    const float4* hrow = (const float4*)(g_h + (size_t)row * D_L);
    float4* hcr = (float4*)(g_hc + (size_t)row * 1024);
    float4 hr[4];
#pragma unroll
    for (int j = 0; j < 4; j++) { hr[j] = hrow[l + 32 * j]; hcr[l + 32 * j] = hr[j]; }
#pragma unroll
    for (int xx = 0; xx < 10; xx++) {
        float sq = 0.f, sk = 0.f;
#pragma unroll
        for (int j = 0; j < 4; j++) {
            const float* wq = &W1s[xx * 1024 + (l + 32 * j) * 4];
            sq = fmaf(hr[j].x, wq[0], fmaf(hr[j].y, wq[1], fmaf(hr[j].z, wq[2], fmaf(hr[j].w, wq[3], sq))));
            sk = fmaf(hr[j].x, wq[512], fmaf(hr[j].y, wq[513], fmaf(hr[j].z, wq[514], fmaf(hr[j].w, wq[515], sk))));
        }
#pragma unroll
        for (int o = 16; o > 0; o >>= 1) {
            sq += __shfl_xor_sync(0xffffffffu, sq, o);
            sk += __shfl_xor_sync(0xffffffffu, sk, o);
        }
        if (l == 0) { g_sq[row * 10 + xx] = sq; g_sk[row * 10 + xx] = sk; }
    }
}

// ---- fused attention (unchanged) ----
__global__ __launch_bounds__(256) void k_attn(const float* __restrict__ mask,
                                              const float* __restrict__ W2) {
    __shared__ float sc[16 * 257];
    __shared__ float sk_s[2560], sq_s[160], w2s[16], madd[256];
    int b = blockIdx.y, q0 = blockIdx.x * 16, tid = threadIdx.x;
    int row0 = b * T_LEN;
    for (int i = tid; i < 2560; i += 256) sk_s[i] = g_sk[row0 * 10 + i];
    if (tid < 160) sq_s[tid] = g_sq[(row0 + q0) * 10 + tid];
    if (tid < 10) w2s[tid] = W2[tid];
    madd[tid] = (mask[row0 + tid] == 0.0f) ? -1e30f : 0.0f;
    __syncthreads();
    {
        float skr[10];
#pragma unroll
        for (int xx = 0; xx < 10; xx++) skr[xx] = sk_s[tid * 10 + xx];
        float mk = madd[tid];
#pragma unroll 4
        for (int q = 0; q < 16; q++) {
            float a = 0.f;
#pragma unroll
            for (int xx = 0; xx < 10; xx++)
                a = fmaf(w2s[xx], htanh(sq_s[q * 10 + xx] + skr[xx]), a);
            sc[q * 257 + tid] = a + mk;
        }
    }
    __syncthreads();
    {
        int w = tid >> 5, l = tid & 31;
        for (int q = w; q < 16; q += 8) {
            float v[8], mx = -1e30f;
#pragma unroll
            for (int j = 0; j < 8; j++) { v[j] = sc[q * 257 + l + 32 * j]; mx = fmaxf(mx, v[j]); }
#pragma unroll
            for (int o = 16; o > 0; o >>= 1) mx = fmaxf(mx, __shfl_xor_sync(0xffffffffu, mx, o));
            float sum = 0.f;
#pragma unroll
            for (int j = 0; j < 8; j++) { v[j] = __expf(v[j] - mx); sum += v[j]; }
#pragma unroll
            for (int o = 16; o > 0; o >>= 1) sum += __shfl_xor_sync(0xffffffffu, sum, o);
            float inv = 1.0f / sum;
#pragma unroll
            for (int j = 0; j < 8; j++) sc[q * 257 + l + 32 * j] = v[j] * inv;
        }
    }
    __syncthreads();
    int qg = tid & 3, dq = tid >> 2;
    float4 acc[4][2];
#pragma unroll
    for (int j = 0; j < 4; j++) { acc[j][0] = make_float4(0,0,0,0); acc[j][1] = make_float4(0,0,0,0); }
#pragma unroll 4
    for (int k = 0; k < 256; k++) {
        const float4* hrow = (const float4*)(g_h + (size_t)(row0 + k) * D_L) + dq * 2;
        float4 h0 = hrow[0], h1 = hrow[1];
#pragma unroll
        for (int j = 0; j < 4; j++) {
            float wq = sc[(qg * 4 + j) * 257 + k];
            acc[j][0].x = fmaf(wq, h0.x, acc[j][0].x); acc[j][0].y = fmaf(wq, h0.y, acc[j][0].y);
            acc[j][0].z = fmaf(wq, h0.z, acc[j][0].z); acc[j][0].w = fmaf(wq, h0.w, acc[j][0].w);
            acc[j][1].x = fmaf(wq, h1.x, acc[j][1].x); acc[j][1].y = fmaf(wq, h1.y, acc[j][1].y);
            acc[j][1].z = fmaf(wq, h1.z, acc[j][1].z); acc[j][1].w = fmaf(wq, h1.w, acc[j][1].w);
        }
    }
#pragma unroll
    for (int j = 0; j < 4; j++) {
        float4* orow = (float4*)(g_hc + (size_t)(row0 + q0 + qg * 4 + j) * 1024 + 512) + dq * 2;
        orow[0] = acc[j][0]; orow[1] = acc[j][1];
    }
}

extern "C" void kernel_launch(void* const* d_in, const int* in_sizes, int n_in,
                              void* d_out, int out_size) {
    const float* x     = (const float*)d_in[0];
    const float* mask  = (const float*)d_in[1];
    const float* Wih_f = (const float*)d_in[2];
    const float* Whh_f = (const float*)d_in[3];
    const float* b_f   = (const float*)d_in[4];
    const float* Wih_b = (const float*)d_in[5];
    const float* Whh_b = (const float*)d_in[6];
    const float* b_b   = (const float*)d_in[7];
    const float* W1    = (const float*)d_in[8];
    const float* W2    = (const float*)d_in[9];
    const float* W3    = (const float*)d_in[10];
    const float* b3    = (const float*)d_in[11];

    float* xzf;  cudaGetSymbolAddress((void**)&xzf, g_xz);
    float* xzb = xzf + XZS;
    float* hc;   cudaGetSymbolAddress((void**)&hc, g_hc);
    float* out = (float*)d_out;

    k_gemm<<<dim3(8, 64, 2), 256>>>(x, D_IN, Wih_f, b_f, xzf, Wih_b, b_b, xzb, G4);
    k_lstm<<<128, 256>>>(Whh_f, Whh_b);
    k_sqsk<<<1024, 256>>>(W1);
    k_attn<<<dim3(16, 32), 256>>>(mask, W2);
    k_gemm<<<dim3(4, 64, 1), 256>>>(hc, 1024, W3, b3, out, W3, b3, out, D_L);
}

// round 12
// speedup vs baseline: 1.3638x; 1.3638x over previous
#include <cuda_runtime.h>
#include <math.h>
#include <stdint.h>

#define T_LEN 256
#define G4    1024
#define D_IN  768
#define D_L   512
#define NROWS 8192
#define XZS   (NROWS * G4)
typedef unsigned long long ull;

__device__ float g_xz[2 * XZS];
__device__ float g_h [NROWS * D_L];
__device__ float g_hc[NROWS * 1024];
__device__ float g_sq[NROWS * 10];
__device__ float g_sk[NROWS * 10];
__device__ unsigned g_cnt[2];
__device__ unsigned g_flag[2 * 64 * 8];

__device__ __forceinline__ unsigned ld_acq(const unsigned* p) {
    unsigned v;
    asm volatile("ld.acquire.gpu.global.u32 %0, [%1];" : "=r"(v) : "l"(p) : "memory");
    return v;
}
__device__ __forceinline__ void st_rel(unsigned* p, unsigned v) {
    asm volatile("st.release.gpu.global.u32 [%0], %1;" :: "l"(p), "r"(v) : "memory");
}
__device__ __forceinline__ unsigned atom_add_rel(unsigned* p, unsigned v) {
    unsigned old;
    asm volatile("atom.add.release.gpu.global.u32 %0, [%1], %2;"
                 : "=r"(old) : "l"(p), "r"(v) : "memory");
    return old;
}
__device__ __forceinline__ void fma2(ull& d, ull a, ull b) {
    asm("fma.rn.f32x2 %0, %1, %2, %0;" : "+l"(d) : "l"(a), "l"(b));
}
__device__ __forceinline__ float hsum2(ull v) {
    float lo, hi; asm("mov.b64 {%0,%1}, %2;" : "=f"(lo), "=f"(hi) : "l"(v));
    return lo + hi;
}
__device__ __forceinline__ float fsig(float x) {
    return __fdividef(1.0f, 1.0f + __expf(-x));
}
__device__ __forceinline__ float ftanh(float x) {
    return fmaf(2.0f, fsig(2.0f * x), -1.0f);
}
__device__ __forceinline__ float htanh(float x) {
    float r; asm("tanh.approx.f32 %0, %1;" : "=f"(r) : "f"(x)); return r;
}
__device__ __forceinline__ uint32_t f2tf(float x) {
    uint32_t r; asm("cvt.rna.tf32.f32 %0, %1;" : "=r"(r) : "f"(x)); return r;
}

// ---- tf32 tensor-core GEMM (unchanged) ----
__global__ __launch_bounds__(256) void k_gemm(const float* __restrict__ A, int Kdim,
                                              const float* __restrict__ W0,
                                              const float* __restrict__ b0,
                                              float* __restrict__ C0,
                                              const float* __restrict__ W1,
                                              const float* __restrict__ b1,
                                              float* __restrict__ C1, int ldc) {
    __shared__ uint32_t As[2][8][136], Bs[2][8][136];
    const float* W    = blockIdx.z ? W1 : W0;
    const float* bias = blockIdx.z ? b1 : b0;
    float*       C    = blockIdx.z ? C1 : C0;
    int tid = threadIdx.x, lane = tid & 31, wid = tid >> 5;
    int m0 = blockIdx.y * 128, n0 = blockIdx.x * 128;
    int mb = (wid >> 2) * 64, nb = (wid & 3) * 32;
    int ar = tid >> 1, ak = (tid & 1) * 4;
    const float* Arow = A + (size_t)(m0 + ar) * Kdim + ak;
    const float* Brow = W + (size_t)(n0 + ar) * Kdim + ak;
    float acc[4][4][4];
#pragma unroll
    for (int i = 0; i < 4; i++)
#pragma unroll
        for (int j = 0; j < 4; j++)
#pragma unroll
            for (int c = 0; c < 4; c++) acc[i][j][c] = 0.f;
    int kq = lane & 3, gq = lane >> 2;
    float4 av = *(const float4*)(Arow);
    float4 bv = *(const float4*)(Brow);
    int buf = 0;
    for (int k0 = 0; k0 < Kdim; k0 += 8) {
        As[buf][ak + 0][ar] = f2tf(av.x); As[buf][ak + 1][ar] = f2tf(av.y);
        As[buf][ak + 2][ar] = f2tf(av.z); As[buf][ak + 3][ar] = f2tf(av.w);
        Bs[buf][ak + 0][ar] = f2tf(bv.x); Bs[buf][ak + 1][ar] = f2tf(bv.y);
        Bs[buf][ak + 2][ar] = f2tf(bv.z); Bs[buf][ak + 3][ar] = f2tf(bv.w);
        __syncthreads();
        if (k0 + 8 < Kdim) {
            av = *(const float4*)(Arow + k0 + 8);
            bv = *(const float4*)(Brow + k0 + 8);
        }
        uint32_t a[4][4], b[4][2];
#pragma unroll
        for (int mf = 0; mf < 4; mf++) {
            int r = mb + mf * 16 + gq;
            a[mf][0] = As[buf][kq][r];     a[mf][1] = As[buf][kq][r + 8];
            a[mf][2] = As[buf][kq + 4][r]; a[mf][3] = As[buf][kq + 4][r + 8];
        }
#pragma unroll
        for (int nf = 0; nf < 4; nf++) {
            int c = nb + nf * 8 + gq;
            b[nf][0] = Bs[buf][kq][c]; b[nf][1] = Bs[buf][kq + 4][c];
        }
#pragma unroll
        for (int mf = 0; mf < 4; mf++)
#pragma unroll
            for (int nf = 0; nf < 4; nf++)
                asm volatile(
                    "mma.sync.aligned.m16n8k8.row.col.f32.tf32.tf32.f32 "
                    "{%0,%1,%2,%3}, {%4,%5,%6,%7}, {%8,%9}, {%0,%1,%2,%3};"
                    : "+f"(acc[mf][nf][0]), "+f"(acc[mf][nf][1]),
                      "+f"(acc[mf][nf][2]), "+f"(acc[mf][nf][3])
                    : "r"(a[mf][0]), "r"(a[mf][1]), "r"(a[mf][2]), "r"(a[mf][3]),
                      "r"(b[nf][0]), "r"(b[nf][1]));
        buf ^= 1;
        __syncthreads();
    }
#pragma unroll
    for (int mf = 0; mf < 4; mf++)
#pragma unroll
        for (int nf = 0; nf < 4; nf++) {
            int row = m0 + mb + mf * 16 + gq;
            int col = n0 + nb + nf * 8 + 2 * kq;
            float b0v = bias[col], b1v = bias[col + 1];
            float* p0 = C + (size_t)row * ldc + col;
            float* p1 = C + (size_t)(row + 8) * ldc + col;
            p0[0] = acc[mf][nf][0] + b0v; p0[1] = acc[mf][nf][1] + b1v;
            p1[0] = acc[mf][nf][2] + b0v; p1[1] = acc[mf][nf][3] + b1v;
        }
}

// ---- persistent LSTM: 64 blocks x 256 threads, BOTH dirs per block ----
#define LSTM_W4   1040
#define LSTM_H4   2080
#define LSTM_ZP   (8 * 528)
#define LSTM_SMEM ((2 * LSTM_W4 + 2 * LSTM_H4) * 16 + LSTM_ZP * 4)

__global__ __launch_bounds__(256) void k_lstm(const float* __restrict__ Whf,
                                              const float* __restrict__ Whb) {
    extern __shared__ char smraw[];
    float4* w4d[2]; float4* h4d[2];
    w4d[0] = (float4*)smraw;
    w4d[1] = w4d[0] + LSTM_W4;
    h4d[0] = w4d[1] + LSTM_W4;
    h4d[1] = h4d[0] + LSTM_H4;
    float* zp = (float*)(h4d[1] + LSTM_H4);
    __shared__ int s_l[2];

    int tid = threadIdx.x, blk = blockIdx.x;
    int u0 = blk * 4;
    unsigned fb0 = g_flag[(0 * 64 + blk) * 8];
    unsigned fb1 = g_flag[(1 * 64 + blk) * 8];

    for (int i = tid; i < 2 * 16 * 64; i += 256) {
        int d = i >> 10, r = i & 1023;
        int gl = r >> 6, kq = r & 63;
        int q = gl >> 2, ul = gl & 3;
        const float* Whh = d ? Whb : Whf;
        w4d[d][gl * 65 + kq] = *(const float4*)(Whh + (size_t)(q * 256 + u0 + ul) * 256 + kq * 4);
    }
    __syncthreads();

    int kseg = tid >> 5, gq = (tid >> 3) & 3, bq = tid & 7;
    int kbase = kseg * 8;
    int a_ul = tid & 3, a_b = tid >> 2;          // tid<128 activation mapping
    float c0 = 0.f, c1 = 0.f;

    for (int s = 0; s < T_LEN; s++) {
        int tt[2]; tt[0] = s; tt[1] = T_LEN - 1 - s;

#pragma unroll
        for (int d = 0; d < 2; d++) {
            int t = tt[d];
            float xzv[4];
            if (tid < 128) {
                const float* xzp = g_xz + (size_t)d * XZS +
                                   (size_t)(a_b * T_LEN + t) * G4 + u0 + a_ul;
#pragma unroll
                for (int g = 0; g < 4; g++) xzv[g] = xzp[g * 256];
            }

            if (s > 0) {
                const float4* w4 = w4d[d];
                const float4* h4 = h4d[d];
                ull acc[4][4];
#pragma unroll
                for (int i = 0; i < 4; i++)
#pragma unroll
                    for (int j = 0; j < 4; j++) acc[i][j] = 0ull;
#pragma unroll
                for (int c = 0; c < 8; c++) {
                    int kq = kbase + c;
                    ulonglong2 wv[4], hv[4];
#pragma unroll
                    for (int i = 0; i < 4; i++) wv[i] = *(const ulonglong2*)&w4[(gq + i * 4) * 65 + kq];
#pragma unroll
                    for (int j = 0; j < 4; j++) hv[j] = *(const ulonglong2*)&h4[(bq + j * 8) * 65 + kq];
#pragma unroll
                    for (int i = 0; i < 4; i++)
#pragma unroll
                        for (int j = 0; j < 4; j++) {
                            fma2(acc[i][j], wv[i].x, hv[j].x);
                            fma2(acc[i][j], wv[i].y, hv[j].y);
                        }
                }
#pragma unroll
                for (int i = 0; i < 4; i++)
#pragma unroll
                    for (int j = 0; j < 4; j++)
                        zp[kseg * 528 + (gq + i * 4) * 33 + (bq + j * 8)] = hsum2(acc[i][j]);
            }
            __syncthreads();                      // zp ready

            if (tid < 128) {
                float zi = xzv[0], zf = xzv[1], zg = xzv[2], zo = xzv[3];
                if (s > 0) {
                    int b0 = (0  + a_ul) * 33 + a_b;
                    int b1 = (4  + a_ul) * 33 + a_b;
                    int b2 = (8  + a_ul) * 33 + a_b;
                    int b3 = (12 + a_ul) * 33 + a_b;
#pragma unroll
                    for (int ks = 0; ks < 8; ks++) {
                        const float* zb = zp + ks * 528;
                        zi += zb[b0]; zf += zb[b1]; zg += zb[b2]; zo += zb[b3];
                    }
                }
                float& cr = d ? c1 : c0;
                cr = fmaf(fsig(zf), cr, fsig(zi) * ftanh(zg));
                g_h[(size_t)(a_b * T_LEN + t) * D_L + d * 256 + u0 + a_ul] =
                    fsig(zo) * ftanh(cr);
            }
            __syncthreads();                      // h stores + zp reads done

            if (tid == 0)
                s_l[d] = (atom_add_rel(&g_cnt[d], 1u) == 63u) ? 1 : 0;
            __syncthreads();
            if (s_l[d]) {
                if (tid == 0) g_cnt[d] = 0u;
                __syncthreads();
                unsigned fb = d ? fb1 : fb0;
                if (tid < 64) st_rel(&g_flag[(d * 64 + tid) * 8], fb + s + 1);
            }
        }

        if (s < T_LEN - 1) {
#pragma unroll
            for (int d = 0; d < 2; d++) {
                unsigned fb = d ? fb1 : fb0;
                if (tid == 0) {
                    while (ld_acq(&g_flag[(d * 64 + blk) * 8]) < fb + s + 1) { }
                }
                __syncthreads();
                int t = tt[d];
                float4* h4 = h4d[d];
                for (int i = tid; i < 32 * 64; i += 256) {
                    int b = i >> 6, kq = i & 63;
                    h4[b * 65 + kq] =
                        *(const float4*)(g_h + (size_t)(b * T_LEN + t) * D_L + d * 256 + kq * 4);
                }
            }
            __syncthreads();
        }
    }
}

// ---- sq/sk projections + copy h into concat buffer (unchanged) ----
__global__ __launch_bounds__(256) void k_sqsk(const float* __restrict__ W1) {
    __shared__ float W1s[10 * 1024];
    int tid = threadIdx.x;
    for (int i = tid; i < 2560; i += 256) ((float4*)W1s)[i] = ((const float4*)W1)[i];
    __syncthreads();
    int w = tid >> 5, l = tid & 31;
    int row = blockIdx.x * 8 + w;
    const float4* hrow = (const float4*)(g_h + (size_t)row * D_L);
    float4* hcr = (float4*)(g_hc + (size_t)row * 1024);
    float4 hr[4];
#pragma unroll
    for (int j = 0; j < 4; j++) { hr[j] = hrow[l + 32 * j]; hcr[l + 32 * j] = hr[j]; }
#pragma unroll
    for (int xx = 0; xx < 10; xx++) {
        float sq = 0.f, sk = 0.f;
#pragma unroll
        for (int j = 0; j < 4; j++) {
            const float* wq = &W1s[xx * 1024 + (l + 32 * j) * 4];
            sq = fmaf(hr[j].x, wq[0], fmaf(hr[j].y, wq[1], fmaf(hr[j].z, wq[2], fmaf(hr[j].w, wq[3], sq))));
            sk = fmaf(hr[j].x, wq[512], fmaf(hr[j].y, wq[513], fmaf(hr[j].z, wq[514], fmaf(hr[j].w, wq[515], sk))));
        }
#pragma unroll
        for (int o = 16; o > 0; o >>= 1) {
            sq += __shfl_xor_sync(0xffffffffu, sq, o);
            sk += __shfl_xor_sync(0xffffffffu, sk, o);
        }
        if (l == 0) { g_sq[row * 10 + xx] = sq; g_sk[row * 10 + xx] = sk; }
    }
}

// ---- fused attention (unchanged) ----
__global__ __launch_bounds__(256) void k_attn(const float* __restrict__ mask,
                                              const float* __restrict__ W2) {
    __shared__ float sc[16 * 257];
    __shared__ float sk_s[2560], sq_s[160], w2s[16], madd[256];
    int b = blockIdx.y, q0 = blockIdx.x * 16, tid = threadIdx.x;
    int row0 = b * T_LEN;
    for (int i = tid; i < 2560; i += 256) sk_s[i] = g_sk[row0 * 10 + i];
    if (tid < 160) sq_s[tid] = g_sq[(row0 + q0) * 10 + tid];
    if (tid < 10) w2s[tid] = W2[tid];
    madd[tid] = (mask[row0 + tid] == 0.0f) ? -1e30f : 0.0f;
    __syncthreads();
    {
        float skr[10];
#pragma unroll
        for (int xx = 0; xx < 10; xx++) skr[xx] = sk_s[tid * 10 + xx];
        float mk = madd[tid];
#pragma unroll 4
        for (int q = 0; q < 16; q++) {
            float a = 0.f;
#pragma unroll
            for (int xx = 0; xx < 10; xx++)
                a = fmaf(w2s[xx], htanh(sq_s[q * 10 + xx] + skr[xx]), a);
            sc[q * 257 + tid] = a + mk;
        }
    }
    __syncthreads();
    {
        int w = tid >> 5, l = tid & 31;
        for (int q = w; q < 16; q += 8) {
            float v[8], mx = -1e30f;
#pragma unroll
            for (int j = 0; j < 8; j++) { v[j] = sc[q * 257 + l + 32 * j]; mx = fmaxf(mx, v[j]); }
#pragma unroll
            for (int o = 16; o > 0; o >>= 1) mx = fmaxf(mx, __shfl_xor_sync(0xffffffffu, mx, o));
            float sum = 0.f;
#pragma unroll
            for (int j = 0; j < 8; j++) { v[j] = __expf(v[j] - mx); sum += v[j]; }
#pragma unroll
            for (int o = 16; o > 0; o >>= 1) sum += __shfl_xor_sync(0xffffffffu, sum, o);
            float inv = 1.0f / sum;
#pragma unroll
            for (int j = 0; j < 8; j++) sc[q * 257 + l + 32 * j] = v[j] * inv;
        }
    }
    __syncthreads();
    int qg = tid & 3, dq = tid >> 2;
    float4 acc[4][2];
#pragma unroll
    for (int j = 0; j < 4; j++) { acc[j][0] = make_float4(0,0,0,0); acc[j][1] = make_float4(0,0,0,0); }
#pragma unroll 4
    for (int k = 0; k < 256; k++) {
        const float4* hrow = (const float4*)(g_h + (size_t)(row0 + k) * D_L) + dq * 2;
        float4 h0 = hrow[0], h1 = hrow[1];
#pragma unroll
        for (int j = 0; j < 4; j++) {
            float wq = sc[(qg * 4 + j) * 257 + k];
            acc[j][0].x = fmaf(wq, h0.x, acc[j][0].x); acc[j][0].y = fmaf(wq, h0.y, acc[j][0].y);
            acc[j][0].z = fmaf(wq, h0.z, acc[j][0].z); acc[j][0].w = fmaf(wq, h0.w, acc[j][0].w);
            acc[j][1].x = fmaf(wq, h1.x, acc[j][1].x); acc[j][1].y = fmaf(wq, h1.y, acc[j][1].y);
            acc[j][1].z = fmaf(wq, h1.z, acc[j][1].z); acc[j][1].w = fmaf(wq, h1.w, acc[j][1].w);
        }
    }
#pragma unroll
    for (int j = 0; j < 4; j++) {
        float4* orow = (float4*)(g_hc + (size_t)(row0 + q0 + qg * 4 + j) * 1024 + 512) + dq * 2;
        orow[0] = acc[j][0]; orow[1] = acc[j][1];
    }
}

extern "C" void kernel_launch(void* const* d_in, const int* in_sizes, int n_in,
                              void* d_out, int out_size) {
    const float* x     = (const float*)d_in[0];
    const float* mask  = (const float*)d_in[1];
    const float* Wih_f = (const float*)d_in[2];
    const float* Whh_f = (const float*)d_in[3];
    const float* b_f   = (const float*)d_in[4];
    const float* Wih_b = (const float*)d_in[5];
    const float* Whh_b = (const float*)d_in[6];
    const float* b_b   = (const float*)d_in[7];
    const float* W1    = (const float*)d_in[8];
    const float* W2    = (const float*)d_in[9];
    const float* W3    = (const float*)d_in[10];
    const float* b3    = (const float*)d_in[11];

    float* xzf;  cudaGetSymbolAddress((void**)&xzf, g_xz);
    float* xzb = xzf + XZS;
    float* hc;   cudaGetSymbolAddress((void**)&hc, g_hc);
    float* out = (float*)d_out;

    cudaFuncSetAttribute(k_lstm, cudaFuncAttributeMaxDynamicSharedMemorySize, LSTM_SMEM);

    k_gemm<<<dim3(8, 64, 2), 256>>>(x, D_IN, Wih_f, b_f, xzf, Wih_b, b_b, xzb, G4);
    k_lstm<<<64, 256, LSTM_SMEM>>>(Whh_f, Whh_b);
    k_sqsk<<<1024, 256>>>(W1);
    k_attn<<<dim3(16, 32), 256>>>(mask, W2);
    k_gemm<<<dim3(4, 64, 1), 256>>>(hc, 1024, W3, b3, out, W3, b3, out, D_L);
}

// round 13
// speedup vs baseline: 2.0534x; 1.5056x over previous
#include <cuda_runtime.h>
#include <math.h>
#include <stdint.h>

#define T_LEN 256
#define G4    1024
#define D_IN  768
#define D_L   512
#define NROWS 8192
#define XZS   (NROWS * G4)
typedef unsigned long long ull;

__device__ float g_xz[2 * XZS];
__device__ float g_h [NROWS * D_L];
__device__ float g_hc[NROWS * 1024];
__device__ float g_sq[NROWS * 10];
__device__ float g_sk[NROWS * 10];
__device__ __align__(16) unsigned g_af[2][64];   // per-block monotonic step flags

__device__ __forceinline__ void st_rel(unsigned* p, unsigned v) {
    asm volatile("st.release.gpu.global.u32 [%0], %1;" :: "l"(p), "r"(v) : "memory");
}
__device__ __forceinline__ uint4 ld_acq4(const uint4* p) {
    uint4 v;
    asm volatile("ld.acquire.gpu.global.v4.u32 {%0,%1,%2,%3}, [%4];"
                 : "=r"(v.x), "=r"(v.y), "=r"(v.z), "=r"(v.w) : "l"(p) : "memory");
    return v;
}
__device__ __forceinline__ void fma2(ull& d, ull a, ull b) {
    asm("fma.rn.f32x2 %0, %1, %2, %0;" : "+l"(d) : "l"(a), "l"(b));
}
__device__ __forceinline__ float hsum2(ull v) {
    float lo, hi; asm("mov.b64 {%0,%1}, %2;" : "=f"(lo), "=f"(hi) : "l"(v));
    return lo + hi;
}
__device__ __forceinline__ float fsig(float x) {
    return __fdividef(1.0f, 1.0f + __expf(-x));
}
__device__ __forceinline__ float ftanh(float x) {
    return fmaf(2.0f, fsig(2.0f * x), -1.0f);
}
__device__ __forceinline__ float htanh(float x) {
    float r; asm("tanh.approx.f32 %0, %1;" : "=f"(r) : "f"(x)); return r;
}
__device__ __forceinline__ uint32_t f2tf(float x) {
    uint32_t r; asm("cvt.rna.tf32.f32 %0, %1;" : "=r"(r) : "f"(x)); return r;
}

// ---- tf32 tensor-core GEMM (unchanged) ----
__global__ __launch_bounds__(256) void k_gemm(const float* __restrict__ A, int Kdim,
                                              const float* __restrict__ W0,
                                              const float* __restrict__ b0,
                                              float* __restrict__ C0,
                                              const float* __restrict__ W1,
                                              const float* __restrict__ b1,
                                              float* __restrict__ C1, int ldc) {
    __shared__ uint32_t As[2][8][136], Bs[2][8][136];
    const float* W    = blockIdx.z ? W1 : W0;
    const float* bias = blockIdx.z ? b1 : b0;
    float*       C    = blockIdx.z ? C1 : C0;
    int tid = threadIdx.x, lane = tid & 31, wid = tid >> 5;
    int m0 = blockIdx.y * 128, n0 = blockIdx.x * 128;
    int mb = (wid >> 2) * 64, nb = (wid & 3) * 32;
    int ar = tid >> 1, ak = (tid & 1) * 4;
    const float* Arow = A + (size_t)(m0 + ar) * Kdim + ak;
    const float* Brow = W + (size_t)(n0 + ar) * Kdim + ak;
    float acc[4][4][4];
#pragma unroll
    for (int i = 0; i < 4; i++)
#pragma unroll
        for (int j = 0; j < 4; j++)
#pragma unroll
            for (int c = 0; c < 4; c++) acc[i][j][c] = 0.f;
    int kq = lane & 3, gq = lane >> 2;
    float4 av = *(const float4*)(Arow);
    float4 bv = *(const float4*)(Brow);
    int buf = 0;
    for (int k0 = 0; k0 < Kdim; k0 += 8) {
        As[buf][ak + 0][ar] = f2tf(av.x); As[buf][ak + 1][ar] = f2tf(av.y);
        As[buf][ak + 2][ar] = f2tf(av.z); As[buf][ak + 3][ar] = f2tf(av.w);
        Bs[buf][ak + 0][ar] = f2tf(bv.x); Bs[buf][ak + 1][ar] = f2tf(bv.y);
        Bs[buf][ak + 2][ar] = f2tf(bv.z); Bs[buf][ak + 3][ar] = f2tf(bv.w);
        __syncthreads();
        if (k0 + 8 < Kdim) {
            av = *(const float4*)(Arow + k0 + 8);
            bv = *(const float4*)(Brow + k0 + 8);
        }
        uint32_t a[4][4], b[4][2];
#pragma unroll
        for (int mf = 0; mf < 4; mf++) {
            int r = mb + mf * 16 + gq;
            a[mf][0] = As[buf][kq][r];     a[mf][1] = As[buf][kq][r + 8];
            a[mf][2] = As[buf][kq + 4][r]; a[mf][3] = As[buf][kq + 4][r + 8];
        }
#pragma unroll
        for (int nf = 0; nf < 4; nf++) {
            int c = nb + nf * 8 + gq;
            b[nf][0] = Bs[buf][kq][c]; b[nf][1] = Bs[buf][kq + 4][c];
        }
#pragma unroll
        for (int mf = 0; mf < 4; mf++)
#pragma unroll
            for (int nf = 0; nf < 4; nf++)
                asm volatile(
                    "mma.sync.aligned.m16n8k8.row.col.f32.tf32.tf32.f32 "
                    "{%0,%1,%2,%3}, {%4,%5,%6,%7}, {%8,%9}, {%0,%1,%2,%3};"
                    : "+f"(acc[mf][nf][0]), "+f"(acc[mf][nf][1]),
                      "+f"(acc[mf][nf][2]), "+f"(acc[mf][nf][3])
                    : "r"(a[mf][0]), "r"(a[mf][1]), "r"(a[mf][2]), "r"(a[mf][3]),
                      "r"(b[nf][0]), "r"(b[nf][1]));
        buf ^= 1;
        __syncthreads();
    }
#pragma unroll
    for (int mf = 0; mf < 4; mf++)
#pragma unroll
        for (int nf = 0; nf < 4; nf++) {
            int row = m0 + mb + mf * 16 + gq;
            int col = n0 + nb + nf * 8 + 2 * kq;
            float b0v = bias[col], b1v = bias[col + 1];
            float* p0 = C + (size_t)row * ldc + col;
            float* p1 = C + (size_t)(row + 8) * ldc + col;
            p0[0] = acc[mf][nf][0] + b0v; p0[1] = acc[mf][nf][1] + b1v;
            p1[0] = acc[mf][nf][2] + b0v; p1[1] = acc[mf][nf][3] + b1v;
        }
}

// ---- persistent LSTM: 128 blocks x 256 threads, flag-broadcast sync ----
#define LSTM_W4   1040
#define LSTM_H4   2080
#define LSTM_ZP   (8 * 528)
#define LSTM_SMEM ((LSTM_W4 + LSTM_H4) * 16 + LSTM_ZP * 4)

__global__ __launch_bounds__(256) void k_lstm(const float* __restrict__ Whf,
                                              const float* __restrict__ Whb) {
    extern __shared__ char smraw[];
    float4* w4 = (float4*)smraw;
    float4* h4 = w4 + LSTM_W4;
    float*  zp = (float*)(h4 + LSTM_H4);

    int tid = threadIdx.x, bi = blockIdx.x;
    int dir = bi >> 6, blk = bi & 63, u0 = blk * 4;
    const float* Whh = dir ? Whb : Whf;
    unsigned fb = g_af[dir][blk];                  // common base (all dir flags equal)

    for (int i = tid; i < 16 * 64; i += 256) {
        int gl = i >> 6, kq = i & 63;
        int q = gl >> 2, ul = gl & 3;
        w4[gl * 65 + kq] = *(const float4*)(Whh + (size_t)(q * 256 + u0 + ul) * 256 + kq * 4);
    }
    __syncthreads();

    int kseg = tid >> 5, gq = (tid >> 3) & 3, bq = tid & 7;
    int kbase = kseg * 8;
    int a_ul = tid & 3, a_b = tid >> 2;            // tid<128 activation mapping
    const float* xz = g_xz + (size_t)dir * XZS;
    float c_reg = 0.f;

    for (int s = 0; s < T_LEN; s++) {
        int t = dir ? (T_LEN - 1 - s) : s;
        float xzv[4];
        if (tid < 128) {
            const float* xzp = xz + (size_t)(a_b * T_LEN + t) * G4 + u0 + a_ul;
#pragma unroll
            for (int g = 0; g < 4; g++) xzv[g] = xzp[g * 256];
        }

        if (s > 0) {
            // wait: all 64 peer flags of this dir >= fb + s
            if (tid < 32) {
                unsigned tgt = fb + (unsigned)s;
                const uint4* fp = (const uint4*)(&g_af[dir][0]);
                unsigned m;
                do {
                    unsigned v = 0xffffffffu;
                    if (tid < 16) {
                        uint4 f = ld_acq4(fp + tid);
                        v = min(min(f.x, f.y), min(f.z, f.w));
                    }
#pragma unroll
                    for (int o = 16; o > 0; o >>= 1)
                        v = min(v, __shfl_xor_sync(0xffffffffu, v, o));
                    m = v;
                } while (m < tgt);
            }
            __syncthreads();

            int tp = dir ? (T_LEN - s) : (s - 1);
            for (int i = tid; i < 32 * 64; i += 256) {
                int b = i >> 6, kq = i & 63;
                h4[b * 65 + kq] =
                    *(const float4*)(g_h + (size_t)(b * T_LEN + tp) * D_L + dir * 256 + kq * 4);
            }
            __syncthreads();

            ull acc[4][4];
#pragma unroll
            for (int i = 0; i < 4; i++)
#pragma unroll
                for (int j = 0; j < 4; j++) acc[i][j] = 0ull;
#pragma unroll
            for (int c = 0; c < 8; c++) {
                int kq = kbase + c;
                ulonglong2 wv[4], hv[4];
#pragma unroll
                for (int i = 0; i < 4; i++) wv[i] = *(const ulonglong2*)&w4[(gq + i * 4) * 65 + kq];
#pragma unroll
                for (int j = 0; j < 4; j++) hv[j] = *(const ulonglong2*)&h4[(bq + j * 8) * 65 + kq];
#pragma unroll
                for (int i = 0; i < 4; i++)
#pragma unroll
                    for (int j = 0; j < 4; j++) {
                        fma2(acc[i][j], wv[i].x, hv[j].x);
                        fma2(acc[i][j], wv[i].y, hv[j].y);
                    }
            }
#pragma unroll
            for (int i = 0; i < 4; i++)
#pragma unroll
                for (int j = 0; j < 4; j++)
                    zp[kseg * 528 + (gq + i * 4) * 33 + (bq + j * 8)] = hsum2(acc[i][j]);
            __syncthreads();
        }

        if (tid < 128) {
            float zi = xzv[0], zf = xzv[1], zg = xzv[2], zo = xzv[3];
            if (s > 0) {
                int b0 = (0  + a_ul) * 33 + a_b;
                int b1 = (4  + a_ul) * 33 + a_b;
                int b2 = (8  + a_ul) * 33 + a_b;
                int b3 = (12 + a_ul) * 33 + a_b;
#pragma unroll
                for (int ks = 0; ks < 8; ks++) {
                    const float* zb = zp + ks * 528;
                    zi += zb[b0]; zf += zb[b1]; zg += zb[b2]; zo += zb[b3];
                }
            }
            c_reg = fmaf(fsig(zf), c_reg, fsig(zi) * ftanh(zg));
            g_h[(size_t)(a_b * T_LEN + t) * D_L + dir * 256 + u0 + a_ul] = fsig(zo) * ftanh(c_reg);
        }
        __syncthreads();                            // h stores + zp/h4 reads done
        if (tid == 0) st_rel(&g_af[dir][blk], fb + (unsigned)s + 1u);
    }
}

// ---- sq/sk projections + copy h into concat buffer (unchanged) ----
__global__ __launch_bounds__(256) void k_sqsk(const float* __restrict__ W1) {
    __shared__ float W1s[10 * 1024];
    int tid = threadIdx.x;
    for (int i = tid; i < 2560; i += 256) ((float4*)W1s)[i] = ((const float4*)W1)[i];
    __syncthreads();
    int w = tid >> 5, l = tid & 31;
    int row = blockIdx.x * 8 + w;
    const float4* hrow = (const float4*)(g_h + (size_t)row * D_L);
    float4* hcr = (float4*)(g_hc + (size_t)row * 1024);
    float4 hr[4];
#pragma unroll
    for (int j = 0; j < 4; j++) { hr[j] = hrow[l + 32 * j]; hcr[l + 32 * j] = hr[j]; }
#pragma unroll
    for (int xx = 0; xx < 10; xx++) {
        float sq = 0.f, sk = 0.f;
#pragma unroll
        for (int j = 0; j < 4; j++) {
            const float* wq = &W1s[xx * 1024 + (l + 32 * j) * 4];
            sq = fmaf(hr[j].x, wq[0], fmaf(hr[j].y, wq[1], fmaf(hr[j].z, wq[2], fmaf(hr[j].w, wq[3], sq))));
            sk = fmaf(hr[j].x, wq[512], fmaf(hr[j].y, wq[513], fmaf(hr[j].z, wq[514], fmaf(hr[j].w, wq[515], sk))));
        }
#pragma unroll
        for (int o = 16; o > 0; o >>= 1) {
            sq += __shfl_xor_sync(0xffffffffu, sq, o);
            sk += __shfl_xor_sync(0xffffffffu, sk, o);
        }
        if (l == 0) { g_sq[row * 10 + xx] = sq; g_sk[row * 10 + xx] = sk; }
    }
}

// ---- fused attention (unchanged) ----
__global__ __launch_bounds__(256) void k_attn(const float* __restrict__ mask,
                                              const float* __restrict__ W2) {
    __shared__ float sc[16 * 257];
    __shared__ float sk_s[2560], sq_s[160], w2s[16], madd[256];
    int b = blockIdx.y, q0 = blockIdx.x * 16, tid = threadIdx.x;
    int row0 = b * T_LEN;
    for (int i = tid; i < 2560; i += 256) sk_s[i] = g_sk[row0 * 10 + i];
    if (tid < 160) sq_s[tid] = g_sq[(row0 + q0) * 10 + tid];
    if (tid < 10) w2s[tid] = W2[tid];
    madd[tid] = (mask[row0 + tid] == 0.0f) ? -1e30f : 0.0f;
    __syncthreads();
    {
        float skr[10];
#pragma unroll
        for (int xx = 0; xx < 10; xx++) skr[xx] = sk_s[tid * 10 + xx];
        float mk = madd[tid];
#pragma unroll 4
        for (int q = 0; q < 16; q++) {
            float a = 0.f;
#pragma unroll
            for (int xx = 0; xx < 10; xx++)
                a = fmaf(w2s[xx], htanh(sq_s[q * 10 + xx] + skr[xx]), a);
            sc[q * 257 + tid] = a + mk;
        }
    }
    __syncthreads();
    {
        int w = tid >> 5, l = tid & 31;
        for (int q = w; q < 16; q += 8) {
            float v[8], mx = -1e30f;
#pragma unroll
            for (int j = 0; j < 8; j++) { v[j] = sc[q * 257 + l + 32 * j]; mx = fmaxf(mx, v[j]); }
#pragma unroll
            for (int o = 16; o > 0; o >>= 1) mx = fmaxf(mx, __shfl_xor_sync(0xffffffffu, mx, o));
            float sum = 0.f;
#pragma unroll
            for (int j = 0; j < 8; j++) { v[j] = __expf(v[j] - mx); sum += v[j]; }
#pragma unroll
            for (int o = 16; o > 0; o >>= 1) sum += __shfl_xor_sync(0xffffffffu, sum, o);
            float inv = 1.0f / sum;
#pragma unroll
            for (int j = 0; j < 8; j++) sc[q * 257 + l + 32 * j] = v[j] * inv;
        }
    }
    __syncthreads();
    int qg = tid & 3, dq = tid >> 2;
    float4 acc[4][2];
#pragma unroll
    for (int j = 0; j < 4; j++) { acc[j][0] = make_float4(0,0,0,0); acc[j][1] = make_float4(0,0,0,0); }
#pragma unroll 4
    for (int k = 0; k < 256; k++) {
        const float4* hrow = (const float4*)(g_h + (size_t)(row0 + k) * D_L) + dq * 2;
        float4 h0 = hrow[0], h1 = hrow[1];
#pragma unroll
        for (int j = 0; j < 4; j++) {
            float wq = sc[(qg * 4 + j) * 257 + k];
            acc[j][0].x = fmaf(wq, h0.x, acc[j][0].x); acc[j][0].y = fmaf(wq, h0.y, acc[j][0].y);
            acc[j][0].z = fmaf(wq, h0.z, acc[j][0].z); acc[j][0].w = fmaf(wq, h0.w, acc[j][0].w);
            acc[j][1].x = fmaf(wq, h1.x, acc[j][1].x); acc[j][1].y = fmaf(wq, h1.y, acc[j][1].y);
            acc[j][1].z = fmaf(wq, h1.z, acc[j][1].z); acc[j][1].w = fmaf(wq, h1.w, acc[j][1].w);
        }
    }
#pragma unroll
    for (int j = 0; j < 4; j++) {
        float4* orow = (float4*)(g_hc + (size_t)(row0 + q0 + qg * 4 + j) * 1024 + 512) + dq * 2;
        orow[0] = acc[j][0]; orow[1] = acc[j][1];
    }
}

extern "C" void kernel_launch(void* const* d_in, const int* in_sizes, int n_in,
                              void* d_out, int out_size) {
    const float* x     = (const float*)d_in[0];
    const float* mask  = (const float*)d_in[1];
    const float* Wih_f = (const float*)d_in[2];
    const float* Whh_f = (const float*)d_in[3];
    const float* b_f   = (const float*)d_in[4];
    const float* Wih_b = (const float*)d_in[5];
    const float* Whh_b = (const float*)d_in[6];
    const float* b_b   = (const float*)d_in[7];
    const float* W1    = (const float*)d_in[8];
    const float* W2    = (const float*)d_in[9];
    const float* W3    = (const float*)d_in[10];
    const float* b3    = (const float*)d_in[11];

    float* xzf;  cudaGetSymbolAddress((void**)&xzf, g_xz);
    float* xzb = xzf + XZS;
    float* hc;   cudaGetSymbolAddress((void**)&hc, g_hc);
    float* out = (float*)d_out;

    cudaFuncSetAttribute(k_lstm, cudaFuncAttributeMaxDynamicSharedMemorySize, LSTM_SMEM);

    k_gemm<<<dim3(8, 64, 2), 256>>>(x, D_IN, Wih_f, b_f, xzf, Wih_b, b_b, xzb, G4);
    k_lstm<<<128, 256, LSTM_SMEM>>>(Whh_f, Whh_b);
    k_sqsk<<<1024, 256>>>(W1);
    k_attn<<<dim3(16, 32), 256>>>(mask, W2);
    k_gemm<<<dim3(4, 64, 1), 256>>>(hc, 1024, W3, b3, out, W3, b3, out, D_L);
}

// round 15
// speedup vs baseline: 2.4160x; 1.1766x over previous
#include <cuda_runtime.h>
#include <math.h>
#include <stdint.h>

#define T_LEN 256
#define G4    1024
#define D_IN  768
#define D_L   512
#define NROWS 8192
#define XZS   (NROWS * G4)
typedef unsigned long long ull;

__device__ float g_xz[2 * XZS];
__device__ float g_h [NROWS * D_L];
__device__ float g_hc[NROWS * 1024];
__device__ float g_sq[NROWS * 10];
__device__ float g_sk[NROWS * 10];
__device__ __align__(64) unsigned g_af[2][4][16];   // [dir][batch-group][unit-group]

__device__ __forceinline__ unsigned ld_acq(const unsigned* p) {
    unsigned v;
    asm volatile("ld.acquire.gpu.global.u32 %0, [%1];" : "=r"(v) : "l"(p) : "memory");
    return v;
}
__device__ __forceinline__ void st_rel(unsigned* p, unsigned v) {
    asm volatile("st.release.gpu.global.u32 [%0], %1;" :: "l"(p), "r"(v) : "memory");
}
__device__ __forceinline__ void fma2(ull& d, ull a, ull b) {
    asm("fma.rn.f32x2 %0, %1, %2, %0;" : "+l"(d) : "l"(a), "l"(b));
}
__device__ __forceinline__ float hsum2(ull v) {
    float lo, hi; asm("mov.b64 {%0,%1}, %2;" : "=f"(lo), "=f"(hi) : "l"(v));
    return lo + hi;
}
__device__ __forceinline__ float fsig(float x) {
    return __fdividef(1.0f, 1.0f + __expf(-x));
}
__device__ __forceinline__ float ftanh(float x) {
    return fmaf(2.0f, fsig(2.0f * x), -1.0f);
}
__device__ __forceinline__ float htanh(float x) {
    float r; asm("tanh.approx.f32 %0, %1;" : "=f"(r) : "f"(x)); return r;
}
__device__ __forceinline__ uint32_t f2tf(float x) {
    uint32_t r; asm("cvt.rna.tf32.f32 %0, %1;" : "=r"(r) : "f"(x)); return r;
}

// ---- tf32 tensor-core GEMM (unchanged) ----
__global__ __launch_bounds__(256) void k_gemm(const float* __restrict__ A, int Kdim,
                                              const float* __restrict__ W0,
                                              const float* __restrict__ b0,
                                              float* __restrict__ C0,
                                              const float* __restrict__ W1,
                                              const float* __restrict__ b1,
                                              float* __restrict__ C1, int ldc) {
    __shared__ uint32_t As[2][8][136], Bs[2][8][136];
    const float* W    = blockIdx.z ? W1 : W0;
    const float* bias = blockIdx.z ? b1 : b0;
    float*       C    = blockIdx.z ? C1 : C0;
    int tid = threadIdx.x, lane = tid & 31, wid = tid >> 5;
    int m0 = blockIdx.y * 128, n0 = blockIdx.x * 128;
    int mb = (wid >> 2) * 64, nb = (wid & 3) * 32;
    int ar = tid >> 1, ak = (tid & 1) * 4;
    const float* Arow = A + (size_t)(m0 + ar) * Kdim + ak;
    const float* Brow = W + (size_t)(n0 + ar) * Kdim + ak;
    float acc[4][4][4];
#pragma unroll
    for (int i = 0; i < 4; i++)
#pragma unroll
        for (int j = 0; j < 4; j++)
#pragma unroll
            for (int c = 0; c < 4; c++) acc[i][j][c] = 0.f;
    int kq = lane & 3, gq = lane >> 2;
    float4 av = *(const float4*)(Arow);
    float4 bv = *(const float4*)(Brow);
    int buf = 0;
    for (int k0 = 0; k0 < Kdim; k0 += 8) {
        As[buf][ak + 0][ar] = f2tf(av.x); As[buf][ak + 1][ar] = f2tf(av.y);
        As[buf][ak + 2][ar] = f2tf(av.z); As[buf][ak + 3][ar] = f2tf(av.w);
        Bs[buf][ak + 0][ar] = f2tf(bv.x); Bs[buf][ak + 1][ar] = f2tf(bv.y);
        Bs[buf][ak + 2][ar] = f2tf(bv.z); Bs[buf][ak + 3][ar] = f2tf(bv.w);
        __syncthreads();
        if (k0 + 8 < Kdim) {
            av = *(const float4*)(Arow + k0 + 8);
            bv = *(const float4*)(Brow + k0 + 8);
        }
        uint32_t a[4][4], b[4][2];
#pragma unroll
        for (int mf = 0; mf < 4; mf++) {
            int r = mb + mf * 16 + gq;
            a[mf][0] = As[buf][kq][r];     a[mf][1] = As[buf][kq][r + 8];
            a[mf][2] = As[buf][kq + 4][r]; a[mf][3] = As[buf][kq + 4][r + 8];
        }
#pragma unroll
        for (int nf = 0; nf < 4; nf++) {
            int c = nb + nf * 8 + gq;
            b[nf][0] = Bs[buf][kq][c]; b[nf][1] = Bs[buf][kq + 4][c];
        }
#pragma unroll
        for (int mf = 0; mf < 4; mf++)
#pragma unroll
            for (int nf = 0; nf < 4; nf++)
                asm volatile(
                    "mma.sync.aligned.m16n8k8.row.col.f32.tf32.tf32.f32 "
                    "{%0,%1,%2,%3}, {%4,%5,%6,%7}, {%8,%9}, {%0,%1,%2,%3};"
                    : "+f"(acc[mf][nf][0]), "+f"(acc[mf][nf][1]),
                      "+f"(acc[mf][nf][2]), "+f"(acc[mf][nf][3])
                    : "r"(a[mf][0]), "r"(a[mf][1]), "r"(a[mf][2]), "r"(a[mf][3]),
                      "r"(b[nf][0]), "r"(b[nf][1]));
        buf ^= 1;
        __syncthreads();
    }
#pragma unroll
    for (int mf = 0; mf < 4; mf++)
#pragma unroll
        for (int nf = 0; nf < 4; nf++) {
            int row = m0 + mb + mf * 16 + gq;
            int col = n0 + nb + nf * 8 + 2 * kq;
            float b0v = bias[col], b1v = bias[col + 1];
            float* p0 = C + (size_t)row * ldc + col;
            float* p1 = C + (size_t)(row + 8) * ldc + col;
            p0[0] = acc[mf][nf][0] + b0v; p0[1] = acc[mf][nf][1] + b1v;
            p1[0] = acc[mf][nf][2] + b0v; p1[1] = acc[mf][nf][3] + b1v;
        }
}

// ---- persistent LSTM: 2D (unit x batch) split; sync domain = 16 blocks ----
// block = (dir, ug 0..15, bg 0..3): units U0=ug*16, batches B0=bg*8
// dyn smem: w4[64 rows][65] f4 | h4[8][65] f4 | zp[8][64*9] f
#define LSTM_W4   (64 * 65)
#define LSTM_H4   (8 * 65)
#define LSTM_ZP   (8 * 576)
#define LSTM_SMEM ((LSTM_W4 + LSTM_H4) * 16 + LSTM_ZP * 4)

__global__ __launch_bounds__(256) void k_lstm(const float* __restrict__ Whf,
                                              const float* __restrict__ Whb) {
    extern __shared__ char smraw[];
    float4* w4 = (float4*)smraw;
    float4* h4 = w4 + LSTM_W4;
    float*  zp = (float*)(h4 + LSTM_H4);

    int tid = threadIdx.x, bi = blockIdx.x;
    int dir = bi >> 6, r = bi & 63;
    int ug = r >> 2, bg = r & 3;
    int U0 = ug * 16, B0 = bg * 8;
    const float* Whh = dir ? Whb : Whf;
    unsigned fb = g_af[dir][bg][ug];               // common base (all flags equal)

    // load weight slice: 64 gate rows (q*16+ul) x 256 k
    for (int i = tid; i < 64 * 64; i += 256) {
        int row = i >> 6, kq = i & 63;
        int q = row >> 4, ul = row & 15;
        w4[row * 65 + kq] = *(const float4*)(Whh + (size_t)(q * 256 + U0 + ul) * 256 + kq * 4);
    }
    __syncthreads();

    int kseg = tid >> 5, lane = tid & 31;
    int rgrp = lane >> 1, bgrp = lane & 1;
    int kbase = kseg * 8;
    int a_ul = tid & 15, a_b = tid >> 4;           // tid<128 activation mapping
    const float* xz = g_xz + (size_t)dir * XZS;
    float c_reg = 0.f;

    for (int s = 0; s < T_LEN; s++) {
        int t = dir ? (T_LEN - 1 - s) : s;
        float xzv[4];
        if (tid < 128) {
            const float* xzp = xz + (size_t)((B0 + a_b) * T_LEN + t) * G4 + U0 + a_ul;
#pragma unroll
            for (int g = 0; g < 4; g++) xzv[g] = xzp[g * 256];
        }

        if (s > 0) {
            // wait: all 16 unit-group flags of (dir,bg) >= fb + s
            if (tid < 32) {
                unsigned tgt = fb + (unsigned)s;
                unsigned v;
                do {
                    v = 0xffffffffu;
                    if (tid < 16) v = ld_acq(&g_af[dir][bg][tid]);
#pragma unroll
                    for (int o = 16; o > 0; o >>= 1)
                        v = min(v, __shfl_xor_sync(0xffffffffu, v, o));
                } while (v < tgt);
            }
            __syncthreads();

            // stage h(prev) for our 8 batches (2 LDG.128 / thread)
            int tp = dir ? (T_LEN - s) : (s - 1);
            for (int i = tid; i < 8 * 64; i += 256) {
                int b = i >> 6, kq = i & 63;
                h4[b * 65 + kq] =
                    *(const float4*)(g_h + (size_t)((B0 + b) * T_LEN + tp) * D_L + dir * 256 + kq * 4);
            }
            __syncthreads();

            ull acc[4][4];
#pragma unroll
            for (int i = 0; i < 4; i++)
#pragma unroll
                for (int j = 0; j < 4; j++) acc[i][j] = 0ull;
#pragma unroll
            for (int c = 0; c < 8; c++) {
                int kq = kbase + c;
                ulonglong2 wv[4], hv[4];
#pragma unroll
                for (int i = 0; i < 4; i++)
                    wv[i] = *(const ulonglong2*)&w4[(rgrp + i * 16) * 65 + kq];
#pragma unroll
                for (int j = 0; j < 4; j++)
                    hv[j] = *(const ulonglong2*)&h4[(bgrp * 4 + j) * 65 + kq];
#pragma unroll
                for (int i = 0; i < 4; i++)
#pragma unroll
                    for (int j = 0; j < 4; j++) {
                        fma2(acc[i][j], wv[i].x, hv[j].x);
                        fma2(acc[i][j], wv[i].y, hv[j].y);
                    }
            }
#pragma unroll
            for (int i = 0; i < 4; i++)
#pragma unroll
                for (int j = 0; j < 4; j++)
                    zp[kseg * 576 + (rgrp + i * 16) * 9 + (bgrp * 4 + j)] = hsum2(acc[i][j]);
            __syncthreads();
        }

        if (tid < 128) {
            float zi = xzv[0], zf = xzv[1], zg = xzv[2], zo = xzv[3];
            if (s > 0) {
                int b0 = (0  + a_ul) * 9 + a_b;
                int b1 = (16 + a_ul) * 9 + a_b;
                int b2 = (32 + a_ul) * 9 + a_b;
                int b3 = (48 + a_ul) * 9 + a_b;
#pragma unroll
                for (int ks = 0; ks < 8; ks++) {
                    const float* zb = zp + ks * 576;
                    zi += zb[b0]; zf += zb[b1]; zg += zb[b2]; zo += zb[b3];
                }
            }
            c_reg = fmaf(fsig(zf), c_reg, fsig(zi) * ftanh(zg));
            g_h[(size_t)((B0 + a_b) * T_LEN + t) * D_L + dir * 256 + U0 + a_ul] =
                fsig(zo) * ftanh(c_reg);
        }
        __syncthreads();                            // h stores + zp/h4 reads done
        if (tid == 0) st_rel(&g_af[dir][bg][ug], fb + (unsigned)s + 1u);
    }
}

// ---- sq/sk projections + copy h into concat buffer (unchanged) ----
__global__ __launch_bounds__(256) void k_sqsk(const float* __restrict__ W1) {
    __shared__ float W1s[10 * 1024];
    int tid = threadIdx.x;
    for (int i = tid; i < 2560; i += 256) ((float4*)W1s)[i] = ((const float4*)W1)[i];
    __syncthreads();
    int w = tid >> 5, l = tid & 31;
    int row = blockIdx.x * 8 + w;
    const float4* hrow = (const float4*)(g_h + (size_t)row * D_L);
    float4* hcr = (float4*)(g_hc + (size_t)row * 1024);
    float4 hr[4];
#pragma unroll
    for (int j = 0; j < 4; j++) { hr[j] = hrow[l + 32 * j]; hcr[l + 32 * j] = hr[j]; }
#pragma unroll
    for (int xx = 0; xx < 10; xx++) {
        float sq = 0.f, sk = 0.f;
#pragma unroll
        for (int j = 0; j < 4; j++) {
            const float* wq = &W1s[xx * 1024 + (l + 32 * j) * 4];
            sq = fmaf(hr[j].x, wq[0], fmaf(hr[j].y, wq[1], fmaf(hr[j].z, wq[2], fmaf(hr[j].w, wq[3], sq))));
            sk = fmaf(hr[j].x, wq[512], fmaf(hr[j].y, wq[513], fmaf(hr[j].z, wq[514], fmaf(hr[j].w, wq[515], sk))));
        }
#pragma unroll
        for (int o = 16; o > 0; o >>= 1) {
            sq += __shfl_xor_sync(0xffffffffu, sq, o);
            sk += __shfl_xor_sync(0xffffffffu, sk, o);
        }
        if (l == 0) { g_sq[row * 10 + xx] = sq; g_sk[row * 10 + xx] = sk; }
    }
}

// ---- fused attention (unchanged) ----
__global__ __launch_bounds__(256) void k_attn(const float* __restrict__ mask,
                                              const float* __restrict__ W2) {
    __shared__ float sc[16 * 257];
    __shared__ float sk_s[2560], sq_s[160], w2s[16], madd[256];
    int b = blockIdx.y, q0 = blockIdx.x * 16, tid = threadIdx.x;
    int row0 = b * T_LEN;
    for (int i = tid; i < 2560; i += 256) sk_s[i] = g_sk[row0 * 10 + i];
    if (tid < 160) sq_s[tid] = g_sq[(row0 + q0) * 10 + tid];
    if (tid < 10) w2s[tid] = W2[tid];
    madd[tid] = (mask[row0 + tid] == 0.0f) ? -1e30f : 0.0f;
    __syncthreads();
    {
        float skr[10];
#pragma unroll
        for (int xx = 0; xx < 10; xx++) skr[xx] = sk_s[tid * 10 + xx];
        float mk = madd[tid];
#pragma unroll 4
        for (int q = 0; q < 16; q++) {
            float a = 0.f;
#pragma unroll
            for (int xx = 0; xx < 10; xx++)
                a = fmaf(w2s[xx], htanh(sq_s[q * 10 + xx] + skr[xx]), a);
            sc[q * 257 + tid] = a + mk;
        }
    }
    __syncthreads();
    {
        int w = tid >> 5, l = tid & 31;
        for (int q = w; q < 16; q += 8) {
            float v[8], mx = -1e30f;
#pragma unroll
            for (int j = 0; j < 8; j++) { v[j] = sc[q * 257 + l + 32 * j]; mx = fmaxf(mx, v[j]); }
#pragma unroll
            for (int o = 16; o > 0; o >>= 1) mx = fmaxf(mx, __shfl_xor_sync(0xffffffffu, mx, o));
            float sum = 0.f;
#pragma unroll
            for (int j = 0; j < 8; j++) { v[j] = __expf(v[j] - mx); sum += v[j]; }
#pragma unroll
            for (int o = 16; o > 0; o >>= 1) sum += __shfl_xor_sync(0xffffffffu, sum, o);
            float inv = 1.0f / sum;
#pragma unroll
            for (int j = 0; j < 8; j++) sc[q * 257 + l + 32 * j] = v[j] * inv;
        }
    }
    __syncthreads();
    int qg = tid & 3, dq = tid >> 2;
    float4 acc[4][2];
#pragma unroll
    for (int j = 0; j < 4; j++) { acc[j][0] = make_float4(0,0,0,0); acc[j][1] = make_float4(0,0,0,0); }
#pragma unroll 4
    for (int k = 0; k < 256; k++) {
        const float4* hrow = (const float4*)(g_h + (size_t)(row0 + k) * D_L) + dq * 2;
        float4 h0 = hrow[0], h1 = hrow[1];
#pragma unroll
        for (int j = 0; j < 4; j++) {
            float wq = sc[(qg * 4 + j) * 257 + k];
            acc[j][0].x = fmaf(wq, h0.x, acc[j][0].x); acc[j][0].y = fmaf(wq, h0.y, acc[j][0].y);
            acc[j][0].z = fmaf(wq, h0.z, acc[j][0].z); acc[j][0].w = fmaf(wq, h0.w, acc[j][0].w);
            acc[j][1].x = fmaf(wq, h1.x, acc[j][1].x); acc[j][1].y = fmaf(wq, h1.y, acc[j][1].y);
            acc[j][1].z = fmaf(wq, h1.z, acc[j][1].z); acc[j][1].w = fmaf(wq, h1.w, acc[j][1].w);
        }
    }
#pragma unroll
    for (int j = 0; j < 4; j++) {
        float4* orow = (float4*)(g_hc + (size_t)(row0 + q0 + qg * 4 + j) * 1024 + 512) + dq * 2;
        orow[0] = acc[j][0]; orow[1] = acc[j][1];
    }
}

extern "C" void kernel_launch(void* const* d_in, const int* in_sizes, int n_in,
                              void* d_out, int out_size) {
    const float* x     = (const float*)d_in[0];
    const float* mask  = (const float*)d_in[1];
    const float* Wih_f = (const float*)d_in[2];
    const float* Whh_f = (const float*)d_in[3];
    const float* b_f   = (const float*)d_in[4];
    const float* Wih_b = (const float*)d_in[5];
    const float* Whh_b = (const float*)d_in[6];
    const float* b_b   = (const float*)d_in[7];
    const float* W1    = (const float*)d_in[8];
    const float* W2    = (const float*)d_in[9];
    const float* W3    = (const float*)d_in[10];
    const float* b3    = (const float*)d_in[11];

    float* xzf;  cudaGetSymbolAddress((void**)&xzf, g_xz);
    float* xzb = xzf + XZS;
    float* hc;   cudaGetSymbolAddress((void**)&hc, g_hc);
    float* out = (float*)d_out;

    cudaFuncSetAttribute(k_lstm, cudaFuncAttributeMaxDynamicSharedMemorySize, LSTM_SMEM);

    k_gemm<<<dim3(8, 64, 2), 256>>>(x, D_IN, Wih_f, b_f, xzf, Wih_b, b_b, xzb, G4);
    k_lstm<<<128, 256, LSTM_SMEM>>>(Whh_f, Whh_b);
    k_sqsk<<<1024, 256>>>(W1);
    k_attn<<<dim3(16, 32), 256>>>(mask, W2);
    k_gemm<<<dim3(4, 64, 1), 256>>>(hc, 1024, W3, b3, out, W3, b3, out, D_L);
}

// round 16
// speedup vs baseline: 2.6216x; 1.0851x over previous
#include <cuda_runtime.h>
#include <math.h>
#include <stdint.h>

#define T_LEN 256
#define G4    1024
#define D_IN  768
#define D_L   512
#define NROWS 8192
#define XZS   (NROWS * G4)
typedef unsigned long long ull;

__device__ float g_xz[2 * XZS];
__device__ float g_h [NROWS * D_L];
__device__ float g_hc[NROWS * 1024];
__device__ float g_sq[NROWS * 10];
__device__ float g_sk[NROWS * 10];
__device__ __align__(64) unsigned g_af[2][8][8];   // [dir][batch-group][unit-group]

__device__ __forceinline__ unsigned ld_acq(const unsigned* p) {
    unsigned v;
    asm volatile("ld.acquire.gpu.global.u32 %0, [%1];" : "=r"(v) : "l"(p) : "memory");
    return v;
}
__device__ __forceinline__ void st_rel(unsigned* p, unsigned v) {
    asm volatile("st.release.gpu.global.u32 [%0], %1;" :: "l"(p), "r"(v) : "memory");
}
__device__ __forceinline__ void fma2(ull& d, ull a, ull b) {
    asm("fma.rn.f32x2 %0, %1, %2, %0;" : "+l"(d) : "l"(a), "l"(b));
}
__device__ __forceinline__ float hsum2(ull v) {
    float lo, hi; asm("mov.b64 {%0,%1}, %2;" : "=f"(lo), "=f"(hi) : "l"(v));
    return lo + hi;
}
__device__ __forceinline__ float fsig(float x) {
    return __fdividef(1.0f, 1.0f + __expf(-x));
}
__device__ __forceinline__ float ftanh(float x) {
    return fmaf(2.0f, fsig(2.0f * x), -1.0f);
}
__device__ __forceinline__ float htanh(float x) {
    float r; asm("tanh.approx.f32 %0, %1;" : "=f"(r) : "f"(x)); return r;
}
__device__ __forceinline__ uint32_t f2tf(float x) {
    uint32_t r; asm("cvt.rna.tf32.f32 %0, %1;" : "=r"(r) : "f"(x)); return r;
}

__global__ void k_nop() {}

// ---- tf32 tensor-core GEMM (unchanged) ----
__global__ __launch_bounds__(256) void k_gemm(const float* __restrict__ A, int Kdim,
                                              const float* __restrict__ W0,
                                              const float* __restrict__ b0,
                                              float* __restrict__ C0,
                                              const float* __restrict__ W1,
                                              const float* __restrict__ b1,
                                              float* __restrict__ C1, int ldc) {
    __shared__ uint32_t As[2][8][136], Bs[2][8][136];
    const float* W    = blockIdx.z ? W1 : W0;
    const float* bias = blockIdx.z ? b1 : b0;
    float*       C    = blockIdx.z ? C1 : C0;
    int tid = threadIdx.x, lane = tid & 31, wid = tid >> 5;
    int m0 = blockIdx.y * 128, n0 = blockIdx.x * 128;
    int mb = (wid >> 2) * 64, nb = (wid & 3) * 32;
    int ar = tid >> 1, ak = (tid & 1) * 4;
    const float* Arow = A + (size_t)(m0 + ar) * Kdim + ak;
    const float* Brow = W + (size_t)(n0 + ar) * Kdim + ak;
    float acc[4][4][4];
#pragma unroll
    for (int i = 0; i < 4; i++)
#pragma unroll
        for (int j = 0; j < 4; j++)
#pragma unroll
            for (int c = 0; c < 4; c++) acc[i][j][c] = 0.f;
    int kq = lane & 3, gq = lane >> 2;
    float4 av = *(const float4*)(Arow);
    float4 bv = *(const float4*)(Brow);
    int buf = 0;
    for (int k0 = 0; k0 < Kdim; k0 += 8) {
        As[buf][ak + 0][ar] = f2tf(av.x); As[buf][ak + 1][ar] = f2tf(av.y);
        As[buf][ak + 2][ar] = f2tf(av.z); As[buf][ak + 3][ar] = f2tf(av.w);
        Bs[buf][ak + 0][ar] = f2tf(bv.x); Bs[buf][ak + 1][ar] = f2tf(bv.y);
        Bs[buf][ak + 2][ar] = f2tf(bv.z); Bs[buf][ak + 3][ar] = f2tf(bv.w);
        __syncthreads();
        if (k0 + 8 < Kdim) {
            av = *(const float4*)(Arow + k0 + 8);
            bv = *(const float4*)(Brow + k0 + 8);
        }
        uint32_t a[4][4], b[4][2];
#pragma unroll
        for (int mf = 0; mf < 4; mf++) {
            int r = mb + mf * 16 + gq;
            a[mf][0] = As[buf][kq][r];     a[mf][1] = As[buf][kq][r + 8];
            a[mf][2] = As[buf][kq + 4][r]; a[mf][3] = As[buf][kq + 4][r + 8];
        }
#pragma unroll
        for (int nf = 0; nf < 4; nf++) {
            int c = nb + nf * 8 + gq;
            b[nf][0] = Bs[buf][kq][c]; b[nf][1] = Bs[buf][kq + 4][c];
        }
#pragma unroll
        for (int mf = 0; mf < 4; mf++)
#pragma unroll
            for (int nf = 0; nf < 4; nf++)
                asm volatile(
                    "mma.sync.aligned.m16n8k8.row.col.f32.tf32.tf32.f32 "
                    "{%0,%1,%2,%3}, {%4,%5,%6,%7}, {%8,%9}, {%0,%1,%2,%3};"
                    : "+f"(acc[mf][nf][0]), "+f"(acc[mf][nf][1]),
                      "+f"(acc[mf][nf][2]), "+f"(acc[mf][nf][3])
                    : "r"(a[mf][0]), "r"(a[mf][1]), "r"(a[mf][2]), "r"(a[mf][3]),
                      "r"(b[nf][0]), "r"(b[nf][1]));
        buf ^= 1;
        __syncthreads();
    }
#pragma unroll
    for (int mf = 0; mf < 4; mf++)
#pragma unroll
        for (int nf = 0; nf < 4; nf++) {
            int row = m0 + mb + mf * 16 + gq;
            int col = n0 + nb + nf * 8 + 2 * kq;
            float b0v = bias[col], b1v = bias[col + 1];
            float* p0 = C + (size_t)row * ldc + col;
            float* p1 = C + (size_t)(row + 8) * ldc + col;
            p0[0] = acc[mf][nf][0] + b0v; p0[1] = acc[mf][nf][1] + b1v;
            p1[0] = acc[mf][nf][2] + b0v; p1[1] = acc[mf][nf][3] + b1v;
        }
}

// ---- persistent LSTM: (32 units x 4 batches) blocks; sync domain = 8 ----
// block = (dir, ug 0..7, bg 0..7): U0=ug*32, B0=bg*4. 128 blocks x 256 thr.
// dyn smem: w4[128 rows][65] f4 | h4[4][65] f4 | zp[8][128*5] f
#define LSTM_W4   (128 * 65)
#define LSTM_H4   (4 * 65)
#define LSTM_ZP   (8 * 640)
#define LSTM_SMEM ((LSTM_W4 + LSTM_H4) * 16 + LSTM_ZP * 4)

__global__ __launch_bounds__(256) void k_lstm(const float* __restrict__ Whf,
                                              const float* __restrict__ Whb) {
    extern __shared__ char smraw[];
    float4* w4 = (float4*)smraw;
    float4* h4 = w4 + LSTM_W4;
    float*  zp = (float*)(h4 + LSTM_H4);

    int tid = threadIdx.x, bi = blockIdx.x;
    int dir = bi >> 6, r = bi & 63;
    int ug = r >> 3, bg = r & 7;
    int U0 = ug * 32, B0 = bg * 4;
    const float* Whh = dir ? Whb : Whf;
    unsigned fb = g_af[dir][bg][ug];               // common base (all flags equal)

    // weight slice: 128 local rows (q*32+ul) x 256 k
    for (int i = tid; i < 128 * 64; i += 256) {
        int row = i >> 6, kq = i & 63;
        int q = row >> 5, ul = row & 31;
        w4[row * 65 + kq] = *(const float4*)(Whh + (size_t)(q * 256 + U0 + ul) * 256 + kq * 4);
    }
    __syncthreads();

    int kseg = tid >> 5, lane = tid & 31;
    int kbase = kseg * 8;
    int a_ul = tid & 31, a_b = tid >> 5;           // tid<128 activation mapping
    const float* xz = g_xz + (size_t)dir * XZS;
    float c_reg = 0.f;

    for (int s = 0; s < T_LEN; s++) {
        int t = dir ? (T_LEN - 1 - s) : s;
        float xzv[4];
        if (tid < 128) {
            const float* xzp = xz + (size_t)((B0 + a_b) * T_LEN + t) * G4 + U0 + a_ul;
#pragma unroll
            for (int g = 0; g < 4; g++) xzv[g] = xzp[g * 256];
        }

        if (s > 0) {
            // wait: all 8 unit-group flags of (dir,bg) >= fb + s
            if (tid < 32) {
                unsigned tgt = fb + (unsigned)s;
                unsigned v;
                do {
                    v = 0xffffffffu;
                    if (tid < 8) v = ld_acq(&g_af[dir][bg][tid]);
#pragma unroll
                    for (int o = 16; o > 0; o >>= 1)
                        v = min(v, __shfl_xor_sync(0xffffffffu, v, o));
                } while (v < tgt);
            }
            __syncthreads();

            // stage h(prev) for our 4 batches (1 LDG.128 / thread)
            int tp = dir ? (T_LEN - s) : (s - 1);
            {
                int b = tid >> 6, kq = tid & 63;
                h4[b * 65 + kq] =
                    *(const float4*)(g_h + (size_t)((B0 + b) * T_LEN + tp) * D_L + dir * 256 + kq * 4);
            }
            __syncthreads();

            ull acc[4][4];
#pragma unroll
            for (int i = 0; i < 4; i++)
#pragma unroll
                for (int j = 0; j < 4; j++) acc[i][j] = 0ull;
#pragma unroll
            for (int c = 0; c < 8; c++) {
                int kq = kbase + c;
                ulonglong2 wv[4], hv[4];
#pragma unroll
                for (int i = 0; i < 4; i++)
                    wv[i] = *(const ulonglong2*)&w4[(lane + i * 32) * 65 + kq];
#pragma unroll
                for (int j = 0; j < 4; j++)
                    hv[j] = *(const ulonglong2*)&h4[j * 65 + kq];
#pragma unroll
                for (int i = 0; i < 4; i++)
#pragma unroll
                    for (int j = 0; j < 4; j++) {
                        fma2(acc[i][j], wv[i].x, hv[j].x);
                        fma2(acc[i][j], wv[i].y, hv[j].y);
                    }
            }
#pragma unroll
            for (int i = 0; i < 4; i++)
#pragma unroll
                for (int j = 0; j < 4; j++)
                    zp[kseg * 640 + (lane + i * 32) * 5 + j] = hsum2(acc[i][j]);
            __syncthreads();
        }

        if (tid < 128) {
            float zi = xzv[0], zf = xzv[1], zg = xzv[2], zo = xzv[3];
            if (s > 0) {
                int b0 = (0  + a_ul) * 5 + a_b;
                int b1 = (32 + a_ul) * 5 + a_b;
                int b2 = (64 + a_ul) * 5 + a_b;
                int b3 = (96 + a_ul) * 5 + a_b;
#pragma unroll
                for (int ks = 0; ks < 8; ks++) {
                    const float* zb = zp + ks * 640;
                    zi += zb[b0]; zf += zb[b1]; zg += zb[b2]; zo += zb[b3];
                }
            }
            c_reg = fmaf(fsig(zf), c_reg, fsig(zi) * ftanh(zg));
            g_h[(size_t)((B0 + a_b) * T_LEN + t) * D_L + dir * 256 + U0 + a_ul] =
                fsig(zo) * ftanh(c_reg);
        }
        __syncthreads();                            // h stores + zp/h4 reads done
        if (tid == 0) st_rel(&g_af[dir][bg][ug], fb + (unsigned)s + 1u);
    }
}

// ---- sq/sk projections + copy h into concat buffer (unchanged) ----
__global__ __launch_bounds__(256) void k_sqsk(const float* __restrict__ W1) {
    __shared__ float W1s[10 * 1024];
    int tid = threadIdx.x;
    for (int i = tid; i < 2560; i += 256) ((float4*)W1s)[i] = ((const float4*)W1)[i];
    __syncthreads();
    int w = tid >> 5, l = tid & 31;
    int row = blockIdx.x * 8 + w;
    const float4* hrow = (const float4*)(g_h + (size_t)row * D_L);
    float4* hcr = (float4*)(g_hc + (size_t)row * 1024);
    float4 hr[4];
#pragma unroll
    for (int j = 0; j < 4; j++) { hr[j] = hrow[l + 32 * j]; hcr[l + 32 * j] = hr[j]; }
#pragma unroll
    for (int xx = 0; xx < 10; xx++) {
        float sq = 0.f, sk = 0.f;
#pragma unroll
        for (int j = 0; j < 4; j++) {
            const float* wq = &W1s[xx * 1024 + (l + 32 * j) * 4];
            sq = fmaf(hr[j].x, wq[0], fmaf(hr[j].y, wq[1], fmaf(hr[j].z, wq[2], fmaf(hr[j].w, wq[3], sq))));
            sk = fmaf(hr[j].x, wq[512], fmaf(hr[j].y, wq[513], fmaf(hr[j].z, wq[514], fmaf(hr[j].w, wq[515], sk))));
        }
#pragma unroll
        for (int o = 16; o > 0; o >>= 1) {
            sq += __shfl_xor_sync(0xffffffffu, sq, o);
            sk += __shfl_xor_sync(0xffffffffu, sk, o);
        }
        if (l == 0) { g_sq[row * 10 + xx] = sq; g_sk[row * 10 + xx] = sk; }
    }
}

// ---- fused attention (unchanged) ----
__global__ __launch_bounds__(256) void k_attn(const float* __restrict__ mask,
                                              const float* __restrict__ W2) {
    __shared__ float sc[16 * 257];
    __shared__ float sk_s[2560], sq_s[160], w2s[16], madd[256];
    int b = blockIdx.y, q0 = blockIdx.x * 16, tid = threadIdx.x;
    int row0 = b * T_LEN;
    for (int i = tid; i < 2560; i += 256) sk_s[i] = g_sk[row0 * 10 + i];
    if (tid < 160) sq_s[tid] = g_sq[(row0 + q0) * 10 + tid];
    if (tid < 10) w2s[tid] = W2[tid];
    madd[tid] = (mask[row0 + tid] == 0.0f) ? -1e30f : 0.0f;
    __syncthreads();
    {
        float skr[10];
#pragma unroll
        for (int xx = 0; xx < 10; xx++) skr[xx] = sk_s[tid * 10 + xx];
        float mk = madd[tid];
#pragma unroll 4
        for (int q = 0; q < 16; q++) {
            float a = 0.f;
#pragma unroll
            for (int xx = 0; xx < 10; xx++)
                a = fmaf(w2s[xx], htanh(sq_s[q * 10 + xx] + skr[xx]), a);
            sc[q * 257 + tid] = a + mk;
        }
    }
    __syncthreads();
    {
        int w = tid >> 5, l = tid & 31;
        for (int q = w; q < 16; q += 8) {
            float v[8], mx = -1e30f;
#pragma unroll
            for (int j = 0; j < 8; j++) { v[j] = sc[q * 257 + l + 32 * j]; mx = fmaxf(mx, v[j]); }
#pragma unroll
            for (int o = 16; o > 0; o >>= 1) mx = fmaxf(mx, __shfl_xor_sync(0xffffffffu, mx, o));
            float sum = 0.f;
#pragma unroll
            for (int j = 0; j < 8; j++) { v[j] = __expf(v[j] - mx); sum += v[j]; }
#pragma unroll
            for (int o = 16; o > 0; o >>= 1) sum += __shfl_xor_sync(0xffffffffu, sum, o);
            float inv = 1.0f / sum;
#pragma unroll
            for (int j = 0; j < 8; j++) sc[q * 257 + l + 32 * j] = v[j] * inv;
        }
    }
    __syncthreads();
    int qg = tid & 3, dq = tid >> 2;
    float4 acc[4][2];
#pragma unroll
    for (int j = 0; j < 4; j++) { acc[j][0] = make_float4(0,0,0,0); acc[j][1] = make_float4(0,0,0,0); }
#pragma unroll 4
    for (int k = 0; k < 256; k++) {
        const float4* hrow = (const float4*)(g_h + (size_t)(row0 + k) * D_L) + dq * 2;
        float4 h0 = hrow[0], h1 = hrow[1];
#pragma unroll
        for (int j = 0; j < 4; j++) {
            float wq = sc[(qg * 4 + j) * 257 + k];
            acc[j][0].x = fmaf(wq, h0.x, acc[j][0].x); acc[j][0].y = fmaf(wq, h0.y, acc[j][0].y);
            acc[j][0].z = fmaf(wq, h0.z, acc[j][0].z); acc[j][0].w = fmaf(wq, h0.w, acc[j][0].w);
            acc[j][1].x = fmaf(wq, h1.x, acc[j][1].x); acc[j][1].y = fmaf(wq, h1.y, acc[j][1].y);
            acc[j][1].z = fmaf(wq, h1.z, acc[j][1].z); acc[j][1].w = fmaf(wq, h1.w, acc[j][1].w);
        }
    }
#pragma unroll
    for (int j = 0; j < 4; j++) {
        float4* orow = (float4*)(g_hc + (size_t)(row0 + q0 + qg * 4 + j) * 1024 + 512) + dq * 2;
        orow[0] = acc[j][0]; orow[1] = acc[j][1];
    }
}

extern "C" void kernel_launch(void* const* d_in, const int* in_sizes, int n_in,
                              void* d_out, int out_size) {
    const float* x     = (const float*)d_in[0];
    const float* mask  = (const float*)d_in[1];
    const float* Wih_f = (const float*)d_in[2];
    const float* Whh_f = (const float*)d_in[3];
    const float* b_f   = (const float*)d_in[4];
    const float* Wih_b = (const float*)d_in[5];
    const float* Whh_b = (const float*)d_in[6];
    const float* b_b   = (const float*)d_in[7];
    const float* W1    = (const float*)d_in[8];
    const float* W2    = (const float*)d_in[9];
    const float* W3    = (const float*)d_in[10];
    const float* b3    = (const float*)d_in[11];

    float* xzf;  cudaGetSymbolAddress((void**)&xzf, g_xz);
    float* xzb = xzf + XZS;
    float* hc;   cudaGetSymbolAddress((void**)&hc, g_hc);
    float* out = (float*)d_out;

    cudaFuncSetAttribute(k_lstm, cudaFuncAttributeMaxDynamicSharedMemorySize, LSTM_SMEM);

    k_gemm<<<dim3(8, 64, 2), 256>>>(x, D_IN, Wih_f, b_f, xzf, Wih_b, b_b, xzb, G4);
    k_nop<<<1, 32>>>();                       // shifts ncu capture slot onto k_lstm
    k_lstm<<<128, 256, LSTM_SMEM>>>(Whh_f, Whh_b);
    k_sqsk<<<1024, 256>>>(W1);
    k_attn<<<dim3(16, 32), 256>>>(mask, W2);
    k_gemm<<<dim3(4, 64, 1), 256>>>(hc, 1024, W3, b3, out, W3, b3, out, D_L);
}